// round 6
// baseline (speedup 1.0000x reference)
#include <cuda_runtime.h>
#include <cuda_bf16.h>

// T=256, BS=128, N=2048. One persistent CTA per batch lane.
#define T_STEPS 256
#define BSZ     128
#define NFEAT   2048
#define BLOCK   128
#define EPT     16                 // elements per thread
#define PAIRS   (EPT / 2)          // 8 packed f32x2 pairs
#define NWARP   (BLOCK / 32)       // 4 warps
#define NPART   (4 * NWARP)        // 16 partials (3-level butterfly)
#define FUDGE_C 1e-4f

typedef unsigned long long ull;

static __device__ __forceinline__ ull pack2(float lo, float hi) {
    ull r; asm("mov.b64 %0, {%1, %2};" : "=l"(r) : "f"(lo), "f"(hi)); return r;
}
static __device__ __forceinline__ ull bcast2(float v) { return pack2(v, v); }
static __device__ __forceinline__ float2 unpack2(ull v) {
    float2 r; asm("mov.b64 {%0, %1}, %2;" : "=f"(r.x), "=f"(r.y) : "l"(v)); return r;
}
static __device__ __forceinline__ ull fma2(ull a, ull b, ull c) {
    ull d; asm("fma.rn.f32x2 %0, %1, %2, %3;" : "=l"(d) : "l"(a), "l"(b), "l"(c)); return d;
}
static __device__ __forceinline__ ull mul2(ull a, ull b) {
    ull d; asm("mul.rn.f32x2 %0, %1, %2;" : "=l"(d) : "l"(a), "l"(b)); return d;
}
static __device__ __forceinline__ ull add2(ull a, ull b) {
    ull d; asm("add.rn.f32x2 %0, %1, %2;" : "=l"(d) : "l"(a), "l"(b)); return d;
}
static __device__ __forceinline__ ull relu2(ull v) {
    float2 f = unpack2(v);
    return pack2(fmaxf(f.x, 0.0f), fmaxf(f.y, 0.0f));
}

__global__ __launch_bounds__(BLOCK, 1)
void elbo_scan_kernel(const float* __restrict__ noises,   // [T,BS]
                      const float* __restrict__ ys,       // [T,BS]
                      const float* __restrict__ qs,       // [T,BS]
                      const float* __restrict__ z_biases, // [N]
                      const float* __restrict__ w_in,     // [N]
                      const float* __restrict__ w_inq,    // [N]
                      const float* __restrict__ p_llr,
                      const float* __restrict__ p_llrd,
                      const float* __restrict__ p_sigb,
                      const float* __restrict__ p_os,
                      const float* __restrict__ p_ufs,
                      const float* __restrict__ p_spwd,
                      const float* __restrict__ p_qsc,
                      const float* __restrict__ p_tq,
                      const float* __restrict__ p_ty,
                      const float* __restrict__ p_te,
                      float* __restrict__ out)            // [T,BS]
{
    const int b    = blockIdx.x;
    const int tid  = threadIdx.x;
    const int wid  = tid >> 5;
    const int lane = tid & 31;

    __shared__ float s_y[T_STEPS];
    __shared__ float s_n[T_STEPS];
    __shared__ float s_q[T_STEPS];
    __shared__ ull   s_p[2][NPART];     // double-buffered (au,ah) packed partials

    s_y[tid]         = ys[tid * BSZ + b];
    s_y[tid + BLOCK] = ys[(tid + BLOCK) * BSZ + b];
    s_n[tid]         = noises[tid * BSZ + b];
    s_n[tid + BLOCK] = noises[(tid + BLOCK) * BSZ + b];
    s_q[tid]         = qs[tid * BSZ + b];
    s_q[tid + BLOCK] = qs[(tid + BLOCK) * BSZ + b];

    const float lr0   = expf(p_llr[0]);
    const float lrd   = expf(p_llrd[0]);
    const float sigb  = p_sigb[0];
    const float osc   = p_os[0];
    const float ufsm1 = p_ufs[0] - 1.0f;
    const float spwd  = log1pf(expf(p_spwd[0]));
    const float qsc   = p_qsc[0];
    const float tq    = 1.0f + log1pf(expf(p_tq[0]));
    const float ty    = 1.0f + log1pf(expf(p_ty[0]));
    const float te    = 1.0f + log1pf(expf(p_te[0]));
    const float itq = 1.0f / tq, ctq = 1.0f - itq;
    const float ity = 1.0f / ty, cty = 1.0f - ity;
    const float ite = 1.0f / te, cte = 1.0f - ite;

    // Register-resident slices (packed f32x2).
    ull win2[PAIRS], wiq2[PAIRS], bia2[PAIRS], W2[PAIRS], hv[PAIRS], P2[PAIRS], Q2[PAIRS];
    {
        const int base = tid * EPT;
        const float4* w4 = reinterpret_cast<const float4*>(w_in + base);
        const float4* q4 = reinterpret_cast<const float4*>(w_inq + base);
        const float4* z4 = reinterpret_cast<const float4*>(z_biases + base);
        #pragma unroll
        for (int v = 0; v < EPT / 4; ++v) {
            float4 a = w4[v], c = q4[v], z = z4[v];
            win2[2*v]   = pack2(a.x, a.y);  win2[2*v+1] = pack2(a.z, a.w);
            wiq2[2*v]   = pack2(c.x, c.y);  wiq2[2*v+1] = pack2(c.z, c.w);
            bia2[2*v]   = pack2(sigb * z.x, sigb * z.y);
            bia2[2*v+1] = pack2(sigb * z.z, sigb * z.w);
        }
    }
    #pragma unroll
    for (int k = 0; k < PAIRS; ++k) W2[k] = 0ull;

    __syncthreads();

    // ---------------- Prologue: step 0 partials + prep for step 1 ----------------
    float lrmult = 1.0f, ylp = 0.0f, elp = 0.0f, cW = 1.0f;
    float qlp = s_q[0] * itq;
    {
        const ull x2  = bcast2(s_n[0]);                    // x_0 = noise_0
        const ull cq2 = bcast2(qsc * qlp);
        ull ah0 = 0ull, ah1 = 0ull;
        #pragma unroll
        for (int k = 0; k < PAIRS; ++k) {
            ull h = relu2(fma2(win2[k], x2, fma2(cq2, wiq2[k], bia2[k])));
            hv[k] = h;
            if (k & 1) ah1 = fma2(h, h, ah1); else ah0 = fma2(h, h, ah0);
        }
        // au = dot(W,h) = 0 at t=0.
        float2 ahf = unpack2(add2(ah0, ah1));
        float au_s = 0.0f;
        float ah_s = ahf.x + ahf.y;
        #pragma unroll
        for (int off = 16; off >= 4; off >>= 1) {
            au_s += __shfl_xor_sync(0xFFFFFFFFu, au_s, off);
            ah_s += __shfl_xor_sync(0xFFFFFFFFu, ah_s, off);
        }
        if (lane < 4) s_p[0][(wid << 2) | lane] = pack2(au_s, ah_s);
    }
    // Prep for step 0's scalar chain and step-1 h (ax/bx) — ylp_{-1}=0.
    float y_c    = s_y[0];
    bool  flag_c = ((__float_as_uint(y_c) & 0x7FFFFFFFu) > 0x7F800000u);
    float byl_c  = 0.0f;
    {
        const float ax = ufsm1 + (flag_c ? ity : 0.0f);
        const float bx = (flag_c ? 0.0f : ity * y_c) + byl_c + s_n[1];
        qlp = fmaf(ctq, qlp, s_q[1] * itq);
        const ull cq2 = bcast2(qsc * qlp);
        const ull axb = bcast2(ax), bxb = bcast2(bx);
        #pragma unroll
        for (int k = 0; k < PAIRS; ++k) {
            P2[k] = mul2(axb, win2[k]);
            Q2[k] = fma2(bxb, win2[k], fma2(cq2, wiq2[k], bia2[k]));
        }
    }

    // ---------------- Main loop: iteration t consumes step-t partials ----------------
    for (int t = 0; t < T_STEPS; ++t) {
        const int buf = t & 1;
        __syncthreads();                       // step-t partials visible

        // Combine 16 packed partials with an add2 tree (broadcast LDS.128).
        const longlong2* pp = reinterpret_cast<const longlong2*>(s_p[buf]);
        longlong2 l0 = pp[0], l1 = pp[1], l2 = pp[2], l3 = pp[3];
        longlong2 l4 = pp[4], l5 = pp[5], l6 = pp[6], l7 = pp[7];
        ull r0 = add2(add2((ull)l0.x, (ull)l0.y), add2((ull)l1.x, (ull)l1.y));
        ull r1 = add2(add2((ull)l2.x, (ull)l2.y), add2((ull)l3.x, (ull)l3.y));
        ull r2 = add2(add2((ull)l4.x, (ull)l4.y), add2((ull)l5.x, (ull)l5.y));
        ull r3 = add2(add2((ull)l6.x, (ull)l6.y), add2((ull)l7.x, (ull)l7.y));
        float2 s = unpack2(add2(add2(r0, r1), add2(r2, r3)));
        const float sumu = s.x, sumh = s.y;

        const float un = cW * sumu;                         // u_t
        if (tid == 0) out[t * BSZ + b] = osc * un;

        // Scalar chain (replicated; gates only the W update).
        const float ysel = flag_c ? un : y_c;
        const float ylpn = fmaf(ity, ysel, byl_c);
        const float en   = ylpn - un;
        ylp = ylpn;
        elp = fmaf(cte, elp, en * ite);
        const float lr = lr0 * lrmult;
        const float le = lr * elp;
        const float v  = fmaf(le * le, sumh, FUDGE_C);
        lrmult *= __expf(-lrd * (v * __frsqrt_rn(v)));
        cW *= fmaf(-lr, spwd, 1.0f);
        const ull leoc2 = bcast2(__fdividef(le, cW));
        const ull un2   = bcast2(un);

        // W_{t+1} update + h_{t+1} = relu(un*P + Q) + next partials (fused).
        ull au0 = 0ull, au1 = 0ull, ah0 = 0ull, ah1 = 0ull;
        #pragma unroll
        for (int k = 0; k < PAIRS; ++k) {
            ull h = relu2(fma2(un2, P2[k], Q2[k]));
            W2[k] = fma2(leoc2, hv[k], W2[k]);
            if (k & 1) { au1 = fma2(W2[k], h, au1); ah1 = fma2(h, h, ah1); }
            else       { au0 = fma2(W2[k], h, au0); ah0 = fma2(h, h, ah0); }
            hv[k] = h;
        }
        float2 auf = unpack2(add2(au0, au1));
        float2 ahf = unpack2(add2(ah0, ah1));
        float au_s = auf.x + auf.y;
        float ah_s = ahf.x + ahf.y;

        // 3-level butterfly; lanes 0-3 hold the 4 residual partial classes.
        #pragma unroll
        for (int off = 16; off >= 4; off >>= 1) {
            au_s += __shfl_xor_sync(0xFFFFFFFFu, au_s, off);
            ah_s += __shfl_xor_sync(0xFFFFFFFFu, ah_s, off);
        }
        if (lane < 4) s_p[buf ^ 1][(wid << 2) | lane] = pack2(au_s, ah_s);

        // Shadow prep for the NEXT iteration (independent of the reduction).
        const int  ti = (t + 1 < T_STEPS) ? (t + 1) : t;     // step index t+1
        const int  tn = (t + 2 < T_STEPS) ? (t + 2) : (T_STEPS - 1);
        y_c    = s_y[ti];
        flag_c = ((__float_as_uint(y_c) & 0x7FFFFFFFu) > 0x7F800000u);
        byl_c  = cty * ylp;
        {
            const float ax = ufsm1 + (flag_c ? ity : 0.0f);
            const float bx = (flag_c ? 0.0f : ity * y_c) + byl_c + s_n[tn];
            qlp = fmaf(ctq, qlp, s_q[tn] * itq);
            const ull cq2 = bcast2(qsc * qlp);
            const ull axb = bcast2(ax), bxb = bcast2(bx);
            #pragma unroll
            for (int k = 0; k < PAIRS; ++k) {
                P2[k] = mul2(axb, win2[k]);
                Q2[k] = fma2(bxb, win2[k], fma2(cq2, wiq2[k], bia2[k]));
            }
        }
    }
}

extern "C" void kernel_launch(void* const* d_in, const int* in_sizes, int n_in,
                              void* d_out, int out_size)
{
    const float* noises = (const float*)d_in[1];
    const float* ys     = (const float*)d_in[2];
    const float* qs     = (const float*)d_in[3];
    const float* zb     = (const float*)d_in[4];
    const float* w_in   = (const float*)d_in[5];
    const float* w_inq  = (const float*)d_in[6];

    elbo_scan_kernel<<<BSZ, BLOCK>>>(noises, ys, qs, zb, w_in, w_inq,
                                     (const float*)d_in[7],  (const float*)d_in[8],
                                     (const float*)d_in[9],  (const float*)d_in[10],
                                     (const float*)d_in[11], (const float*)d_in[12],
                                     (const float*)d_in[13], (const float*)d_in[14],
                                     (const float*)d_in[15], (const float*)d_in[16],
                                     (float*)d_out);
}